// round 12
// baseline (speedup 1.0000x reference)

#include <cuda_runtime.h>
#include <cuda_bf16.h>
#include <mma.h>
#include <cstdint>
#include <cstddef>
#include <type_traits>

using namespace nvcuda;

#define BATCH 8
#define CCH   512
#define NPIX  4096
#define CQD   64

// ---------------- static scratch (no runtime allocation allowed) ----------------
__device__ __nv_bfloat16 g_xb[(size_t)BATCH * CCH * NPIX];     // x in bf16
__device__ __nv_bfloat16 g_Wq[CQD * CCH];
__device__ __nv_bfloat16 g_Wk[CQD * CCH];
__device__ __nv_bfloat16 g_Wv[CCH * CCH];
__device__ __nv_bfloat16 g_q[(size_t)BATCH * CQD * NPIX];
__device__ __nv_bfloat16 g_k[(size_t)BATCH * CQD * NPIX];
__device__ __nv_bfloat16 g_v[(size_t)BATCH * CCH * NPIX];
__device__ __nv_bfloat16 g_attn[(size_t)BATCH * NPIX * NPIX];  // exp(scores), unnormalized
__device__ float         g_rspart[(size_t)BATCH * 8 * NPIX];   // per-jgroup rowsum partials
__device__ float         g_rowsum[(size_t)BATCH * NPIX];

// ---------------- helpers ----------------
__device__ __forceinline__ uint32_t smem_u32(const void* p) {
    uint32_t a;
    asm("{ .reg .u64 t; cvta.to.shared.u64 t, %1; cvt.u32.u64 %0, t; }" : "=r"(a) : "l"(p));
    return a;
}
__device__ __forceinline__ void cpa16(uint32_t dst, const void* src) {
    asm volatile("cp.async.cg.shared.global [%0], [%1], 16;" :: "r"(dst), "l"(src));
}
#define CP_COMMIT() asm volatile("cp.async.commit_group;" ::: "memory")
#define CP_WAIT(n)  asm volatile("cp.async.wait_group %0;" :: "n"(n) : "memory")

// ---------------- fp32 -> bf16 cast (vectorized) ----------------
__global__ void cast_kernel(const float* __restrict__ in,
                            __nv_bfloat16* __restrict__ out, size_t n4) {
    size_t i = (size_t)blockIdx.x * blockDim.x + threadIdx.x;
    if (i < n4) {
        float4 f = reinterpret_cast<const float4*>(in)[i];
        __nv_bfloat162 a = __floats2bfloat162_rn(f.x, f.y);
        __nv_bfloat162 b = __floats2bfloat162_rn(f.z, f.w);
        uint2 u;
        u.x = *reinterpret_cast<unsigned*>(&a);
        u.y = *reinterpret_cast<unsigned*>(&b);
        reinterpret_cast<uint2*>(out)[i] = u;
    }
}

// ---------------- rowsum partial reduce: 8 jgroups -> 1 ----------------
__global__ void rs_reduce(const float* __restrict__ rspart,
                          float* __restrict__ rowsum) {
    int idx = blockIdx.x * blockDim.x + threadIdx.x;   // b*NPIX + i
    if (idx < BATCH * NPIX) {
        int b = idx / NPIX, i = idx - b * NPIX;
        float s = 0.0f;
#pragma unroll
        for (int jg = 0; jg < 8; ++jg)
            s += rspart[((size_t)b * 8 + jg) * NPIX + i];
        rowsum[idx] = s;
    }
}

// ============ scores kernel: Q-resident, 4 pipelined j-tiles, fused rowsum ============
// attn[i,j] = exp(sum_d q[d,i]*k[d,j]); partial row sums per (CTA's 512-j group).
// A = q col-major [64][i], resident. B = k row-major [64][j], double buffered.
// 128 threads, 4 warps of 64x64.
__global__ void __launch_bounds__(128, 2)
scores_pipe(const __nv_bfloat16* __restrict__ q, const __nv_bfloat16* __restrict__ k,
            __nv_bfloat16* __restrict__ attn, float* __restrict__ rspart)
{
    constexpr int LDS = 136;                 // 128 + 8 pad (halves)
    constexpr int TILE = 64 * LDS;           // halves per 64x128 tile
    extern __shared__ char dsm[];
    __nv_bfloat16* smA = reinterpret_cast<__nv_bfloat16*>(dsm);     // [64][136]
    __nv_bfloat16* smB = smA + TILE;                                // 2 x [64][136]
    float* stage = reinterpret_cast<float*>(smB + 2 * TILE);        // [4][256]
    float* aux = stage + 4 * 256;                                   // [2][128]
    const uint32_t smA_u = smem_u32(smA);
    const uint32_t smB_u = smem_u32(smB);

    const int b = blockIdx.z;
    const int jg = blockIdx.x;               // 0..7, covers j in [jg*512, jg*512+512)
    const int i0 = blockIdx.y * 128;
    const int tid = threadIdx.x;
    const int wid = tid >> 5, lane = tid & 31;
    const int wm0 = (wid & 1) * 64;          // WGM = 2
    const int wn0 = (wid >> 1) * 64;

    const size_t sQ = (size_t)CQD * NPIX;
    const __nv_bfloat16* qb = q + (size_t)b * sQ;
    const __nv_bfloat16* kb = k + (size_t)b * sQ;
    __nv_bfloat16* attnb = attn + (size_t)b * NPIX * NPIX;

    // zero aux
    aux[tid] = 0.0f;
    aux[128 + tid] = 0.0f;

    // prologue: load A (q block) + B(j-tile 0); 8 chunks each of 128 threads
#pragma unroll
    for (int it = 0; it < 8; ++it) {
        int idx = tid + it * 128;
        int r = idx >> 4, cv = idx & 15;
        cpa16(smA_u + (uint32_t)(r * LDS + cv * 8) * 2,
              qb + (size_t)r * NPIX + i0 + cv * 8);
    }
    {
        const int j0 = jg * 512;
#pragma unroll
        for (int it = 0; it < 8; ++it) {
            int idx = tid + it * 128;
            int r = idx >> 4, cv = idx & 15;
            cpa16(smB_u + (uint32_t)(r * LDS + cv * 8) * 2,
                  kb + (size_t)r * NPIX + j0 + cv * 8);
        }
    }
    CP_COMMIT();

    for (int jt = 0; jt < 4; ++jt) {
        const int cur = jt & 1;
        if (jt + 1 < 4) {
            const int j0 = jg * 512 + (jt + 1) * 128;
            const uint32_t bbuf = smB_u + (uint32_t)((cur ^ 1) * TILE) * 2;
#pragma unroll
            for (int it = 0; it < 8; ++it) {
                int idx = tid + it * 128;
                int r = idx >> 4, cv = idx & 15;
                cpa16(bbuf + (uint32_t)(r * LDS + cv * 8) * 2,
                      kb + (size_t)r * NPIX + j0 + cv * 8);
            }
            CP_COMMIT();
            CP_WAIT(1);
        } else {
            CP_WAIT(0);
        }
        __syncthreads();

        // MMA: S(128x128) = A^T * B over K=64
        wmma::fragment<wmma::accumulator, 16, 16, 16, float> acc[4][4];
#pragma unroll
        for (int i = 0; i < 4; i++)
#pragma unroll
            for (int j = 0; j < 4; j++) wmma::fill_fragment(acc[i][j], 0.0f);

        const __nv_bfloat16* b0 = smB + cur * TILE;
#pragma unroll
        for (int kk = 0; kk < 64; kk += 16) {
            wmma::fragment<wmma::matrix_a, 16, 16, 16, __nv_bfloat16, wmma::col_major> af[4];
            wmma::fragment<wmma::matrix_b, 16, 16, 16, __nv_bfloat16, wmma::row_major> bfr[4];
#pragma unroll
            for (int i = 0; i < 4; i++)
                wmma::load_matrix_sync(af[i], smA + kk * LDS + wm0 + i * 16, LDS);
#pragma unroll
            for (int j = 0; j < 4; j++)
                wmma::load_matrix_sync(bfr[j], b0 + kk * LDS + wn0 + j * 16, LDS);
#pragma unroll
            for (int i = 0; i < 4; i++)
#pragma unroll
                for (int j = 0; j < 4; j++)
                    wmma::mma_sync(acc[i][j], af[i], bfr[j], acc[i][j]);
        }
        __syncthreads();

        // epilogue: exp -> attn, fused partial rowsum via shuffle + shared add
        const int jbase = jg * 512 + jt * 128;
#pragma unroll
        for (int i = 0; i < 4; i++) {
#pragma unroll
            for (int j = 0; j < 4; j++) {
                wmma::store_matrix_sync(&stage[wid * 256], acc[i][j], 16, wmma::mem_row_major);
                __syncwarp();
                int rowBase = i0 + wm0 + i * 16;
                int colBase = jbase + wn0 + j * 16;
#pragma unroll
                for (int u = 0; u < 8; ++u) {
                    int e = lane + 32 * u;
                    int r = e >> 4, c = e & 15;
                    float val = __expf(stage[wid * 256 + e]);
                    attnb[(size_t)(rowBase + r) * NPIX + colBase + c] = __float2bfloat16(val);
                    float s = val;
                    s += __shfl_xor_sync(0xffffffffu, s, 1);
                    s += __shfl_xor_sync(0xffffffffu, s, 2);
                    s += __shfl_xor_sync(0xffffffffu, s, 4);
                    s += __shfl_xor_sync(0xffffffffu, s, 8);
                    if ((lane & 15) == 0)
                        aux[(wid >> 1) * 128 + wm0 + i * 16 + r] += s;
                }
                __syncwarp();
            }
        }
        __syncthreads();
    }

    // write per-CTA partial rowsum
    float vtot = aux[tid] + aux[128 + tid];
    rspart[((size_t)b * 8 + jg) * NPIX + i0 + tid] = vtot;
}
static constexpr size_t SCORES_SMEM = (size_t)3 * 64 * 136 * 2 + 4 * 256 * 4 + 2 * 128 * 4 + 128;

// ============ pipelined 128x128 GEMM: cp.async 2-stage, 4 warps of 64x64 ============
// EPI 1: bf16 (acc + bias[row]); EPI 2: fp32 (gamma/rowsum[col]*acc + xres)
template<bool AROW, bool BROW, int EPI>
__global__ void __launch_bounds__(128, 2)
gemm_pipe(const __nv_bfloat16* __restrict__ A, size_t strideA, int lda,
          const __nv_bfloat16* __restrict__ Bm, size_t strideB, int ldb,
          void* __restrict__ Cm, size_t strideC, int ldc,
          const float* __restrict__ bias,
          const float* __restrict__ gamma,
          const float* __restrict__ xres, size_t strideX,
          const float* __restrict__ rowsum,
          int M, int N, int K)
{
    constexpr int BM = 128, BN = 128, BK = 64, WM = 64, WN = 64;
    constexpr int WGM = BM / WM;
    constexpr int MI = WM / 16, NI = WN / 16;
    constexpr int SA_R = AROW ? BM : BK, SA_C = AROW ? BK : BM;
    constexpr int SB_R = BROW ? BK : BN, SB_C = BROW ? BN : BK;
    constexpr int LDA_S = SA_C + 8, LDB_S = SB_C + 8;
    constexpr int AELEM = SA_R * LDA_S;
    constexpr int BELEM = SB_R * LDB_S;
    constexpr int CVA = SA_C / 8, CVB = SB_C / 8;
    constexpr int ITA = (SA_R * CVA) / 128;
    constexpr int ITB = (SB_R * CVB) / 128;

    extern __shared__ char dsm[];
    __nv_bfloat16* smA = reinterpret_cast<__nv_bfloat16*>(dsm);
    __nv_bfloat16* smB = smA + 2 * AELEM;
    float* stage = reinterpret_cast<float*>(smB + 2 * BELEM);
    float* aux = stage + 4 * 256;
    const uint32_t smA_u = smem_u32(smA);
    const uint32_t smB_u = smem_u32(smB);

    const int b = blockIdx.z;
    const __nv_bfloat16* Ab = A + strideA * (size_t)b;
    const __nv_bfloat16* Bb = Bm + strideB * (size_t)b;
    const size_t cb = strideC * (size_t)b;

    const int blockM = blockIdx.y * BM;
    const int blockN = blockIdx.x * BN;
    const int tid = threadIdx.x;
    const int wid = tid >> 5, lane = tid & 31;
    const int wm0 = (wid % WGM) * WM;
    const int wn0 = (wid / WGM) * WN;

    using ALayout = typename std::conditional<AROW, wmma::row_major, wmma::col_major>::type;
    using BLayout = typename std::conditional<BROW, wmma::row_major, wmma::col_major>::type;

    wmma::fragment<wmma::accumulator, 16, 16, 16, float> acc[MI][NI];
#pragma unroll
    for (int i = 0; i < MI; i++)
#pragma unroll
        for (int j = 0; j < NI; j++) wmma::fill_fragment(acc[i][j], 0.0f);

#pragma unroll
    for (int it = 0; it < ITA; ++it) {
        int idx = tid + it * 128;
        int r = idx / CVA, cv = idx % CVA;
        const __nv_bfloat16* src = AROW
            ? Ab + (size_t)(blockM + r) * lda + cv * 8
            : Ab + (size_t)r * lda + blockM + cv * 8;
        cpa16(smA_u + (uint32_t)(r * LDA_S + cv * 8) * 2, src);
    }
#pragma unroll
    for (int it = 0; it < ITB; ++it) {
        int idx = tid + it * 128;
        int r = idx / CVB, cv = idx % CVB;
        const __nv_bfloat16* src = BROW
            ? Bb + (size_t)r * ldb + blockN + cv * 8
            : Bb + (size_t)(blockN + r) * ldb + cv * 8;
        cpa16(smB_u + (uint32_t)(r * LDB_S + cv * 8) * 2, src);
    }
    CP_COMMIT();

    const int T = K / BK;
    for (int t = 0; t < T; ++t) {
        const int cur = t & 1;
        if (t + 1 < T) {
            const int k0 = (t + 1) * BK;
            const uint32_t abuf = smA_u + (uint32_t)((cur ^ 1) * AELEM) * 2;
            const uint32_t bbuf = smB_u + (uint32_t)((cur ^ 1) * BELEM) * 2;
#pragma unroll
            for (int it = 0; it < ITA; ++it) {
                int idx = tid + it * 128;
                int r = idx / CVA, cv = idx % CVA;
                const __nv_bfloat16* src = AROW
                    ? Ab + (size_t)(blockM + r) * lda + k0 + cv * 8
                    : Ab + (size_t)(k0 + r) * lda + blockM + cv * 8;
                cpa16(abuf + (uint32_t)(r * LDA_S + cv * 8) * 2, src);
            }
#pragma unroll
            for (int it = 0; it < ITB; ++it) {
                int idx = tid + it * 128;
                int r = idx / CVB, cv = idx % CVB;
                const __nv_bfloat16* src = BROW
                    ? Bb + (size_t)(k0 + r) * ldb + blockN + cv * 8
                    : Bb + (size_t)(blockN + r) * ldb + k0 + cv * 8;
                cpa16(bbuf + (uint32_t)(r * LDB_S + cv * 8) * 2, src);
            }
            CP_COMMIT();
            CP_WAIT(1);
        } else {
            CP_WAIT(0);
        }
        __syncthreads();

        const __nv_bfloat16* a0 = smA + cur * AELEM;
        const __nv_bfloat16* b0 = smB + cur * BELEM;
#pragma unroll
        for (int kk = 0; kk < BK; kk += 16) {
            wmma::fragment<wmma::matrix_a, 16, 16, 16, __nv_bfloat16, ALayout> af[MI];
            wmma::fragment<wmma::matrix_b, 16, 16, 16, __nv_bfloat16, BLayout> bfr[NI];
#pragma unroll
            for (int i = 0; i < MI; i++) {
                const __nv_bfloat16* p = AROW ? a0 + (wm0 + i * 16) * LDA_S + kk
                                              : a0 + kk * LDA_S + wm0 + i * 16;
                wmma::load_matrix_sync(af[i], p, LDA_S);
            }
#pragma unroll
            for (int j = 0; j < NI; j++) {
                const __nv_bfloat16* p = BROW ? b0 + kk * LDB_S + wn0 + j * 16
                                              : b0 + (wn0 + j * 16) * LDB_S + kk;
                wmma::load_matrix_sync(bfr[j], p, LDB_S);
            }
#pragma unroll
            for (int i = 0; i < MI; i++)
#pragma unroll
                for (int j = 0; j < NI; j++)
                    wmma::mma_sync(acc[i][j], af[i], bfr[j], acc[i][j]);
        }
        __syncthreads();
    }

    if (EPI == 2) {
        aux[tid] = gamma[0] / rowsum[(size_t)b * N + blockN + tid];
        __syncthreads();
    }

#pragma unroll
    for (int i = 0; i < MI; i++) {
#pragma unroll
        for (int j = 0; j < NI; j++) {
            wmma::store_matrix_sync(&stage[wid * 256], acc[i][j], 16, wmma::mem_row_major);
            __syncwarp();
            int rowBase = blockM + wm0 + i * 16;
            int colBase = blockN + wn0 + j * 16;
#pragma unroll
            for (int e = lane; e < 256; e += 32) {
                int r = e >> 4, c = e & 15;
                float val = stage[wid * 256 + e];
                size_t o = (size_t)(rowBase + r) * ldc + colBase + c;
                if (EPI == 1) {
                    ((__nv_bfloat16*)Cm)[cb + o] = __float2bfloat16(val + bias[rowBase + r]);
                } else {  // EPI 2
                    ((float*)Cm)[cb + o] =
                        val * aux[wn0 + j * 16 + c] + xres[strideX * (size_t)b + o];
                }
            }
            __syncwarp();
        }
    }
}

static constexpr size_t pipe_smem(bool AROW, bool BROW) {
    int SA_R = AROW ? 128 : 64, SA_C = AROW ? 64 : 128;
    int SB_R = BROW ? 64 : 128, SB_C = BROW ? 128 : 64;
    return (size_t)2 * (SA_R * (SA_C + 8) + SB_R * (SB_C + 8)) * 2 +
           (size_t)4 * 256 * 4 + 512;
}

// ---------- register-prefetch GEMM (q/k projections) ----------
template<int BM, int BN, int BK, int WM, int WN, bool AROW, bool BROW>
__global__ void __launch_bounds__((BM / WM) * (BN / WN) * 32)
gemm_bf16(const __nv_bfloat16* __restrict__ A, size_t strideA, int lda,
          const __nv_bfloat16* __restrict__ Bm, size_t strideB, int ldb,
          void* __restrict__ Cm, size_t strideC, int ldc,
          const float* __restrict__ bias,
          int M, int N, int K)
{
    constexpr int WGM = BM / WM, WGN = BN / WN, NW = WGM * WGN;
    constexpr int MI = WM / 16, NI = WN / 16;
    constexpr int SA_R = AROW ? BM : BK, SA_C = AROW ? BK : BM;
    constexpr int SB_R = BROW ? BK : BN, SB_C = BROW ? BN : BK;
    constexpr int CVA = SA_C / 8, CVB = SB_C / 8;
    constexpr int ITA = (SA_R * CVA) / (NW * 32);
    constexpr int ITB = (SB_R * CVB) / (NW * 32);

    __shared__ __nv_bfloat16 smA[SA_R][SA_C + 8];
    __shared__ __nv_bfloat16 smB[SB_R][SB_C + 8];
    __shared__ float stage[NW][16 * 16];

    const int b = blockIdx.z;
    const __nv_bfloat16* Ab = A + strideA * (size_t)b;
    const __nv_bfloat16* Bb = Bm + strideB * (size_t)b;
    const size_t cb = strideC * (size_t)b;

    const int blockM = blockIdx.y * BM;
    const int blockN = blockIdx.x * BN;
    const int tid = threadIdx.x;
    const int wid = tid >> 5, lane = tid & 31;
    const int wm0 = (wid % WGM) * WM;
    const int wn0 = (wid / WGM) * WN;

    using ALayout = typename std::conditional<AROW, wmma::row_major, wmma::col_major>::type;
    using BLayout = typename std::conditional<BROW, wmma::row_major, wmma::col_major>::type;

    wmma::fragment<wmma::accumulator, 16, 16, 16, float> acc[MI][NI];
#pragma unroll
    for (int i = 0; i < MI; i++)
#pragma unroll
        for (int j = 0; j < NI; j++) wmma::fill_fragment(acc[i][j], 0.0f);

#pragma unroll
    for (int it = 0; it < ITA; ++it) {
        int idx = tid + it * NW * 32;
        int r = idx / CVA, cv = idx % CVA;
        const __nv_bfloat16* src = AROW
            ? Ab + (size_t)(blockM + r) * lda + cv * 8
            : Ab + (size_t)r * lda + blockM + cv * 8;
        *reinterpret_cast<uint4*>(&smA[r][cv * 8]) = *reinterpret_cast<const uint4*>(src);
    }
#pragma unroll
    for (int it = 0; it < ITB; ++it) {
        int idx = tid + it * NW * 32;
        int r = idx / CVB, cv = idx % CVB;
        const __nv_bfloat16* src = BROW
            ? Bb + (size_t)r * ldb + blockN + cv * 8
            : Bb + (size_t)(blockN + r) * ldb + cv * 8;
        *reinterpret_cast<uint4*>(&smB[r][cv * 8]) = *reinterpret_cast<const uint4*>(src);
    }
    __syncthreads();

    const int T = K / BK;
    for (int t = 0; t < T; ++t) {
        uint4 pra[ITA], prb[ITB];
        if (t + 1 < T) {
            const int k0 = (t + 1) * BK;
#pragma unroll
            for (int it = 0; it < ITA; ++it) {
                int idx = tid + it * NW * 32;
                int r = idx / CVA, cv = idx % CVA;
                const __nv_bfloat16* src = AROW
                    ? Ab + (size_t)(blockM + r) * lda + k0 + cv * 8
                    : Ab + (size_t)(k0 + r) * lda + blockM + cv * 8;
                pra[it] = *reinterpret_cast<const uint4*>(src);
            }
#pragma unroll
            for (int it = 0; it < ITB; ++it) {
                int idx = tid + it * NW * 32;
                int r = idx / CVB, cv = idx % CVB;
                const __nv_bfloat16* src = BROW
                    ? Bb + (size_t)(k0 + r) * ldb + blockN + cv * 8
                    : Bb + (size_t)(blockN + r) * ldb + k0 + cv * 8;
                prb[it] = *reinterpret_cast<const uint4*>(src);
            }
        }

#pragma unroll
        for (int kk = 0; kk < BK; kk += 16) {
            wmma::fragment<wmma::matrix_a, 16, 16, 16, __nv_bfloat16, ALayout> af[MI];
            wmma::fragment<wmma::matrix_b, 16, 16, 16, __nv_bfloat16, BLayout> bfr[NI];
#pragma unroll
            for (int i = 0; i < MI; i++) {
                const __nv_bfloat16* p = AROW ? &smA[wm0 + i * 16][kk]
                                              : &smA[kk][wm0 + i * 16];
                wmma::load_matrix_sync(af[i], p, SA_C + 8);
            }
#pragma unroll
            for (int j = 0; j < NI; j++) {
                const __nv_bfloat16* p = BROW ? &smB[kk][wn0 + j * 16]
                                              : &smB[wn0 + j * 16][kk];
                wmma::load_matrix_sync(bfr[j], p, SB_C + 8);
            }
#pragma unroll
            for (int i = 0; i < MI; i++)
#pragma unroll
                for (int j = 0; j < NI; j++)
                    wmma::mma_sync(acc[i][j], af[i], bfr[j], acc[i][j]);
        }
        __syncthreads();

        if (t + 1 < T) {
#pragma unroll
            for (int it = 0; it < ITA; ++it) {
                int idx = tid + it * NW * 32;
                int r = idx / CVA, cv = idx % CVA;
                *reinterpret_cast<uint4*>(&smA[r][cv * 8]) = pra[it];
            }
#pragma unroll
            for (int it = 0; it < ITB; ++it) {
                int idx = tid + it * NW * 32;
                int r = idx / CVB, cv = idx % CVB;
                *reinterpret_cast<uint4*>(&smB[r][cv * 8]) = prb[it];
            }
            __syncthreads();
        }
    }

#pragma unroll
    for (int i = 0; i < MI; i++) {
#pragma unroll
        for (int j = 0; j < NI; j++) {
            wmma::store_matrix_sync(&stage[wid][0], acc[i][j], 16, wmma::mem_row_major);
            __syncwarp();
            int rowBase = blockM + wm0 + i * 16;
            int colBase = blockN + wn0 + j * 16;
#pragma unroll
            for (int e = lane; e < 256; e += 32) {
                int r = e >> 4, c = e & 15;
                float val = stage[wid][e];
                size_t o = (size_t)(rowBase + r) * ldc + colBase + c;
                ((__nv_bfloat16*)Cm)[cb + o] = __float2bfloat16(val + bias[rowBase + r]);
            }
            __syncwarp();
        }
    }
}

// ---------------- launch ----------------
extern "C" void kernel_launch(void* const* d_in, const int* in_sizes, int n_in,
                              void* d_out, int out_size) {
    const float* x     = (const float*)d_in[0];
    const float* Wq    = (const float*)d_in[1];
    const float* bq    = (const float*)d_in[2];
    const float* Wk    = (const float*)d_in[3];
    const float* bk    = (const float*)d_in[4];
    const float* Wv    = (const float*)d_in[5];
    const float* bv    = (const float*)d_in[6];
    const float* gamma = (const float*)d_in[7];

    __nv_bfloat16 *xb, *wq, *wk, *wv, *q, *k, *v, *attn;
    float *rspart, *rowsum;
    cudaGetSymbolAddress((void**)&xb, g_xb);
    cudaGetSymbolAddress((void**)&wq, g_Wq);
    cudaGetSymbolAddress((void**)&wk, g_Wk);
    cudaGetSymbolAddress((void**)&wv, g_Wv);
    cudaGetSymbolAddress((void**)&q, g_q);
    cudaGetSymbolAddress((void**)&k, g_k);
    cudaGetSymbolAddress((void**)&v, g_v);
    cudaGetSymbolAddress((void**)&attn, g_attn);
    cudaGetSymbolAddress((void**)&rspart, g_rspart);
    cudaGetSymbolAddress((void**)&rowsum, g_rowsum);

    const size_t sX = (size_t)CCH * NPIX;
    const size_t sQ = (size_t)CQD * NPIX;
    const size_t sS = (size_t)NPIX * NPIX;

    // casts
    {
        size_t n4 = (size_t)BATCH * sX / 4;
        cast_kernel<<<(unsigned)((n4 + 255) / 256), 256>>>(x, xb, n4);
        size_t nq4 = (size_t)CQD * CCH / 4;
        cast_kernel<<<(unsigned)((nq4 + 255) / 256), 256>>>(Wq, wq, nq4);
        cast_kernel<<<(unsigned)((nq4 + 255) / 256), 256>>>(Wk, wk, nq4);
        size_t nv4 = (size_t)CCH * CCH / 4;
        cast_kernel<<<(unsigned)((nv4 + 255) / 256), 256>>>(Wv, wv, nv4);
    }

    // q = Wq @ xb + bq ; k = Wk @ xb + bk   [64 x 4096] per batch, bf16 out
    {
        dim3 g(NPIX / 128, CQD / 64, BATCH);
        gemm_bf16<64, 128, 64, 32, 32, true, true><<<g, 256>>>(
            wq, 0, CCH, xb, sX, NPIX, q, sQ, NPIX, bq, CQD, NPIX, CCH);
        gemm_bf16<64, 128, 64, 32, 32, true, true><<<g, 256>>>(
            wk, 0, CCH, xb, sX, NPIX, k, sQ, NPIX, bk, CQD, NPIX, CCH);
    }

    // v = Wv @ xb + bv   [512 x 4096] per batch, bf16 out
    {
        auto kfn = gemm_pipe<true, true, 1>;
        size_t sm = pipe_smem(true, true);
        cudaFuncSetAttribute(kfn, cudaFuncAttributeMaxDynamicSharedMemorySize, (int)sm);
        dim3 g(NPIX / 128, CCH / 128, BATCH);
        kfn<<<g, 128, sm>>>(wv, 0, CCH, xb, sX, NPIX, v, sX, NPIX, bv,
                            nullptr, nullptr, 0, nullptr, CCH, NPIX, CCH);
    }

    // attn = exp(q^T k) with fused partial rowsums (Q-resident pipelined kernel)
    {
        cudaFuncSetAttribute(scores_pipe,
                             cudaFuncAttributeMaxDynamicSharedMemorySize, (int)SCORES_SMEM);
        dim3 g(8, NPIX / 128, BATCH);
        scores_pipe<<<g, 128, SCORES_SMEM>>>(q, k, attn, rspart);
    }

    // rowsum = sum of 8 partials
    rs_reduce<<<(BATCH * NPIX + 255) / 256, 256>>>(rspart, rowsum);

    // out[c,i] = gamma/rowsum[i] * sum_j v[c,j]*attn[i,j] + x[c,i]  -> fp32
    {
        auto kfn = gemm_pipe<true, false, 2>;
        size_t sm = pipe_smem(true, false);
        cudaFuncSetAttribute(kfn, cudaFuncAttributeMaxDynamicSharedMemorySize, (int)sm);
        dim3 g(NPIX / 128, CCH / 128, BATCH);
        kfn<<<g, 128, sm>>>(v, sX, NPIX, attn, sS, NPIX, d_out, sX, NPIX, nullptr,
                            gamma, x, sX, rowsum, CCH, NPIX, NPIX);
    }
}

// round 13
// speedup vs baseline: 1.3779x; 1.3779x over previous

#include <cuda_runtime.h>
#include <cuda_bf16.h>
#include <mma.h>
#include <cstdint>
#include <cstddef>
#include <type_traits>

using namespace nvcuda;

#define BATCH 8
#define CCH   512
#define NPIX  4096
#define CQD   64

// ---------------- static scratch (no runtime allocation allowed) ----------------
__device__ __nv_bfloat16 g_xb[(size_t)BATCH * CCH * NPIX];     // x in bf16
__device__ __nv_bfloat16 g_Wq[CQD * CCH];
__device__ __nv_bfloat16 g_Wk[CQD * CCH];
__device__ __nv_bfloat16 g_Wv[CCH * CCH];
__device__ __nv_bfloat16 g_q[(size_t)BATCH * CQD * NPIX];
__device__ __nv_bfloat16 g_k[(size_t)BATCH * CQD * NPIX];
__device__ __nv_bfloat16 g_v[(size_t)BATCH * CCH * NPIX];
__device__ __nv_bfloat16 g_attn[(size_t)BATCH * NPIX * NPIX];  // exp(scores), unnormalized
__device__ float         g_rowsum[(size_t)BATCH * NPIX];

// ---------------- helpers ----------------
__device__ __forceinline__ uint32_t smem_u32(const void* p) {
    uint32_t a;
    asm("{ .reg .u64 t; cvta.to.shared.u64 t, %1; cvt.u32.u64 %0, t; }" : "=r"(a) : "l"(p));
    return a;
}
__device__ __forceinline__ void cpa16(uint32_t dst, const void* src) {
    asm volatile("cp.async.cg.shared.global [%0], [%1], 16;" :: "r"(dst), "l"(src));
}
#define CP_COMMIT() asm volatile("cp.async.commit_group;" ::: "memory")
#define CP_WAIT(n)  asm volatile("cp.async.wait_group %0;" :: "n"(n) : "memory")

// ---------------- fp32 -> bf16 cast (vectorized) ----------------
__global__ void cast_kernel(const float* __restrict__ in,
                            __nv_bfloat16* __restrict__ out, size_t n4) {
    size_t i = (size_t)blockIdx.x * blockDim.x + threadIdx.x;
    if (i < n4) {
        float4 f = reinterpret_cast<const float4*>(in)[i];
        __nv_bfloat162 a = __floats2bfloat162_rn(f.x, f.y);
        __nv_bfloat162 b = __floats2bfloat162_rn(f.z, f.w);
        uint2 u;
        u.x = *reinterpret_cast<unsigned*>(&a);
        u.y = *reinterpret_cast<unsigned*>(&b);
        reinterpret_cast<uint2*>(out)[i] = u;
    }
}

// ---------------- rowsum reduction over attn rows (proven round-11 kernel) ----------------
__global__ void rowsum_kernel(const __nv_bfloat16* __restrict__ attn,
                              float* __restrict__ rowsum) {
    size_t row = blockIdx.x;
    const uint2* src = reinterpret_cast<const uint2*>(attn + row * NPIX);
    int t = threadIdx.x;
    float s = 0.0f;
#pragma unroll
    for (int i = 0; i < 8; ++i) {
        uint2 u = src[t + 128 * i];
        __nv_bfloat162 h0 = *reinterpret_cast<__nv_bfloat162*>(&u.x);
        __nv_bfloat162 h1 = *reinterpret_cast<__nv_bfloat162*>(&u.y);
        s += __bfloat162float(__low2bfloat16(h0)) + __bfloat162float(__high2bfloat16(h0));
        s += __bfloat162float(__low2bfloat16(h1)) + __bfloat162float(__high2bfloat16(h1));
    }
#pragma unroll
    for (int o = 16; o > 0; o >>= 1) s += __shfl_xor_sync(0xffffffffu, s, o);
    __shared__ float red[4];
    if ((t & 31) == 0) red[t >> 5] = s;
    __syncthreads();
    if (t == 0) rowsum[row] = red[0] + red[1] + red[2] + red[3];
}

// ============ scores kernel: Q-resident, 4 pipelined j-tiles, PLAIN epilogue ============
// attn[i,j] = exp(sum_d q[d,i]*k[d,j]).  128 threads, 4 warps of 64x64.
__global__ void __launch_bounds__(128, 2)
scores_pipe(const __nv_bfloat16* __restrict__ q, const __nv_bfloat16* __restrict__ k,
            __nv_bfloat16* __restrict__ attn)
{
    constexpr int LDS = 136;                 // 128 + 8 pad (halves)
    constexpr int TILE = 64 * LDS;
    extern __shared__ char dsm[];
    __nv_bfloat16* smA = reinterpret_cast<__nv_bfloat16*>(dsm);     // [64][136]
    __nv_bfloat16* smB = smA + TILE;                                // 2 x [64][136]
    float* stage = reinterpret_cast<float*>(smB + 2 * TILE);        // [4][256]
    const uint32_t smA_u = smem_u32(smA);
    const uint32_t smB_u = smem_u32(smB);

    const int b = blockIdx.z;
    const int jg = blockIdx.x;               // 0..7, j in [jg*512, jg*512+512)
    const int i0 = blockIdx.y * 128;
    const int tid = threadIdx.x;
    const int wid = tid >> 5, lane = tid & 31;
    const int wm0 = (wid & 1) * 64;
    const int wn0 = (wid >> 1) * 64;

    const size_t sQ = (size_t)CQD * NPIX;
    const __nv_bfloat16* qb = q + (size_t)b * sQ;
    const __nv_bfloat16* kb = k + (size_t)b * sQ;
    __nv_bfloat16* attnb = attn + (size_t)b * NPIX * NPIX;

    // prologue: A (q block, resident) + B(j-tile 0)
#pragma unroll
    for (int it = 0; it < 8; ++it) {
        int idx = tid + it * 128;
        int r = idx >> 4, cv = idx & 15;
        cpa16(smA_u + (uint32_t)(r * LDS + cv * 8) * 2,
              qb + (size_t)r * NPIX + i0 + cv * 8);
    }
    {
        const int j0 = jg * 512;
#pragma unroll
        for (int it = 0; it < 8; ++it) {
            int idx = tid + it * 128;
            int r = idx >> 4, cv = idx & 15;
            cpa16(smB_u + (uint32_t)(r * LDS + cv * 8) * 2,
                  kb + (size_t)r * NPIX + j0 + cv * 8);
        }
    }
    CP_COMMIT();

    for (int jt = 0; jt < 4; ++jt) {
        const int cur = jt & 1;
        if (jt + 1 < 4) {
            const int j0 = jg * 512 + (jt + 1) * 128;
            const uint32_t bbuf = smB_u + (uint32_t)((cur ^ 1) * TILE) * 2;
#pragma unroll
            for (int it = 0; it < 8; ++it) {
                int idx = tid + it * 128;
                int r = idx >> 4, cv = idx & 15;
                cpa16(bbuf + (uint32_t)(r * LDS + cv * 8) * 2,
                      kb + (size_t)r * NPIX + j0 + cv * 8);
            }
            CP_COMMIT();
            CP_WAIT(1);
        } else {
            CP_WAIT(0);
        }
        __syncthreads();

        // MMA: S(128x128) = A^T * B over K=64
        wmma::fragment<wmma::accumulator, 16, 16, 16, float> acc[4][4];
#pragma unroll
        for (int i = 0; i < 4; i++)
#pragma unroll
            for (int j = 0; j < 4; j++) wmma::fill_fragment(acc[i][j], 0.0f);

        const __nv_bfloat16* b0 = smB + cur * TILE;
#pragma unroll
        for (int kk = 0; kk < 64; kk += 16) {
            wmma::fragment<wmma::matrix_a, 16, 16, 16, __nv_bfloat16, wmma::col_major> af[4];
            wmma::fragment<wmma::matrix_b, 16, 16, 16, __nv_bfloat16, wmma::row_major> bfr[4];
#pragma unroll
            for (int i = 0; i < 4; i++)
                wmma::load_matrix_sync(af[i], smA + kk * LDS + wm0 + i * 16, LDS);
#pragma unroll
            for (int j = 0; j < 4; j++)
                wmma::load_matrix_sync(bfr[j], b0 + kk * LDS + wn0 + j * 16, LDS);
#pragma unroll
            for (int i = 0; i < 4; i++)
#pragma unroll
                for (int j = 0; j < 4; j++)
                    wmma::mma_sync(acc[i][j], af[i], bfr[j], acc[i][j]);
        }
        __syncthreads();

        // plain epilogue: exp -> attn, vectorized bf16x2 stores
        const int jbase = jg * 512 + jt * 128;
#pragma unroll
        for (int i = 0; i < 4; i++) {
#pragma unroll
            for (int j = 0; j < 4; j++) {
                wmma::store_matrix_sync(&stage[wid * 256], acc[i][j], 16, wmma::mem_row_major);
                __syncwarp();
                int rowBase = i0 + wm0 + i * 16;
                int colBase = jbase + wn0 + j * 16;
#pragma unroll
                for (int p = 0; p < 4; ++p) {
                    int pi = lane + 32 * p;          // pair index 0..127
                    int r = pi >> 3, c = (pi & 7) * 2;
                    float e0 = __expf(stage[wid * 256 + r * 16 + c]);
                    float e1 = __expf(stage[wid * 256 + r * 16 + c + 1]);
                    __nv_bfloat162 h = __floats2bfloat162_rn(e0, e1);
                    *reinterpret_cast<uint32_t*>(
                        &attnb[(size_t)(rowBase + r) * NPIX + colBase + c]) =
                        *reinterpret_cast<uint32_t*>(&h);
                }
                __syncwarp();
            }
        }
        __syncthreads();
    }
}
static constexpr size_t SCORES_SMEM = (size_t)3 * 64 * 136 * 2 + 4 * 256 * 4 + 128;

// ============ pipelined 128x128 GEMM: cp.async 2-stage, 4 warps of 64x64 ============
// EPI 1: bf16 (acc + bias[row]); EPI 2: fp32 (gamma/rowsum[col]*acc + xres)
template<bool AROW, bool BROW, int EPI>
__global__ void __launch_bounds__(128, 2)
gemm_pipe(const __nv_bfloat16* __restrict__ A, size_t strideA, int lda,
          const __nv_bfloat16* __restrict__ Bm, size_t strideB, int ldb,
          void* __restrict__ Cm, size_t strideC, int ldc,
          const float* __restrict__ bias,
          const float* __restrict__ gamma,
          const float* __restrict__ xres, size_t strideX,
          const float* __restrict__ rowsum,
          int M, int N, int K)
{
    constexpr int BM = 128, BN = 128, BK = 64, WM = 64, WN = 64;
    constexpr int WGM = BM / WM;
    constexpr int MI = WM / 16, NI = WN / 16;
    constexpr int SA_R = AROW ? BM : BK, SA_C = AROW ? BK : BM;
    constexpr int SB_R = BROW ? BK : BN, SB_C = BROW ? BN : BK;
    constexpr int LDA_S = SA_C + 8, LDB_S = SB_C + 8;
    constexpr int AELEM = SA_R * LDA_S;
    constexpr int BELEM = SB_R * LDB_S;
    constexpr int CVA = SA_C / 8, CVB = SB_C / 8;
    constexpr int ITA = (SA_R * CVA) / 128;
    constexpr int ITB = (SB_R * CVB) / 128;

    extern __shared__ char dsm[];
    __nv_bfloat16* smA = reinterpret_cast<__nv_bfloat16*>(dsm);
    __nv_bfloat16* smB = smA + 2 * AELEM;
    float* stage = reinterpret_cast<float*>(smB + 2 * BELEM);
    float* aux = stage + 4 * 256;
    const uint32_t smA_u = smem_u32(smA);
    const uint32_t smB_u = smem_u32(smB);

    const int b = blockIdx.z;
    const __nv_bfloat16* Ab = A + strideA * (size_t)b;
    const __nv_bfloat16* Bb = Bm + strideB * (size_t)b;
    const size_t cb = strideC * (size_t)b;

    const int blockM = blockIdx.y * BM;
    const int blockN = blockIdx.x * BN;
    const int tid = threadIdx.x;
    const int wid = tid >> 5, lane = tid & 31;
    const int wm0 = (wid % WGM) * WM;
    const int wn0 = (wid / WGM) * WN;

    using ALayout = typename std::conditional<AROW, wmma::row_major, wmma::col_major>::type;
    using BLayout = typename std::conditional<BROW, wmma::row_major, wmma::col_major>::type;

    wmma::fragment<wmma::accumulator, 16, 16, 16, float> acc[MI][NI];
#pragma unroll
    for (int i = 0; i < MI; i++)
#pragma unroll
        for (int j = 0; j < NI; j++) wmma::fill_fragment(acc[i][j], 0.0f);

#pragma unroll
    for (int it = 0; it < ITA; ++it) {
        int idx = tid + it * 128;
        int r = idx / CVA, cv = idx % CVA;
        const __nv_bfloat16* src = AROW
            ? Ab + (size_t)(blockM + r) * lda + cv * 8
            : Ab + (size_t)r * lda + blockM + cv * 8;
        cpa16(smA_u + (uint32_t)(r * LDA_S + cv * 8) * 2, src);
    }
#pragma unroll
    for (int it = 0; it < ITB; ++it) {
        int idx = tid + it * 128;
        int r = idx / CVB, cv = idx % CVB;
        const __nv_bfloat16* src = BROW
            ? Bb + (size_t)r * ldb + blockN + cv * 8
            : Bb + (size_t)(blockN + r) * ldb + cv * 8;
        cpa16(smB_u + (uint32_t)(r * LDB_S + cv * 8) * 2, src);
    }
    CP_COMMIT();

    const int T = K / BK;
    for (int t = 0; t < T; ++t) {
        const int cur = t & 1;
        if (t + 1 < T) {
            const int k0 = (t + 1) * BK;
            const uint32_t abuf = smA_u + (uint32_t)((cur ^ 1) * AELEM) * 2;
            const uint32_t bbuf = smB_u + (uint32_t)((cur ^ 1) * BELEM) * 2;
#pragma unroll
            for (int it = 0; it < ITA; ++it) {
                int idx = tid + it * 128;
                int r = idx / CVA, cv = idx % CVA;
                const __nv_bfloat16* src = AROW
                    ? Ab + (size_t)(blockM + r) * lda + k0 + cv * 8
                    : Ab + (size_t)(k0 + r) * lda + blockM + cv * 8;
                cpa16(abuf + (uint32_t)(r * LDA_S + cv * 8) * 2, src);
            }
#pragma unroll
            for (int it = 0; it < ITB; ++it) {
                int idx = tid + it * 128;
                int r = idx / CVB, cv = idx % CVB;
                const __nv_bfloat16* src = BROW
                    ? Bb + (size_t)(k0 + r) * ldb + blockN + cv * 8
                    : Bb + (size_t)(blockN + r) * ldb + k0 + cv * 8;
                cpa16(bbuf + (uint32_t)(r * LDB_S + cv * 8) * 2, src);
            }
            CP_COMMIT();
            CP_WAIT(1);
        } else {
            CP_WAIT(0);
        }
        __syncthreads();

        const __nv_bfloat16* a0 = smA + cur * AELEM;
        const __nv_bfloat16* b0 = smB + cur * BELEM;
#pragma unroll
        for (int kk = 0; kk < BK; kk += 16) {
            wmma::fragment<wmma::matrix_a, 16, 16, 16, __nv_bfloat16, ALayout> af[MI];
            wmma::fragment<wmma::matrix_b, 16, 16, 16, __nv_bfloat16, BLayout> bfr[NI];
#pragma unroll
            for (int i = 0; i < MI; i++) {
                const __nv_bfloat16* p = AROW ? a0 + (wm0 + i * 16) * LDA_S + kk
                                              : a0 + kk * LDA_S + wm0 + i * 16;
                wmma::load_matrix_sync(af[i], p, LDA_S);
            }
#pragma unroll
            for (int j = 0; j < NI; j++) {
                const __nv_bfloat16* p = BROW ? b0 + kk * LDB_S + wn0 + j * 16
                                              : b0 + (wn0 + j * 16) * LDB_S + kk;
                wmma::load_matrix_sync(bfr[j], p, LDB_S);
            }
#pragma unroll
            for (int i = 0; i < MI; i++)
#pragma unroll
                for (int j = 0; j < NI; j++)
                    wmma::mma_sync(acc[i][j], af[i], bfr[j], acc[i][j]);
        }
        __syncthreads();
    }

    if (EPI == 2) {
        aux[tid] = gamma[0] / rowsum[(size_t)b * N + blockN + tid];
        __syncthreads();
    }

#pragma unroll
    for (int i = 0; i < MI; i++) {
#pragma unroll
        for (int j = 0; j < NI; j++) {
            wmma::store_matrix_sync(&stage[wid * 256], acc[i][j], 16, wmma::mem_row_major);
            __syncwarp();
            int rowBase = blockM + wm0 + i * 16;
            int colBase = blockN + wn0 + j * 16;
#pragma unroll
            for (int e = lane; e < 256; e += 32) {
                int r = e >> 4, c = e & 15;
                float val = stage[wid * 256 + e];
                size_t o = (size_t)(rowBase + r) * ldc + colBase + c;
                if (EPI == 1) {
                    ((__nv_bfloat16*)Cm)[cb + o] = __float2bfloat16(val + bias[rowBase + r]);
                } else {  // EPI 2
                    ((float*)Cm)[cb + o] =
                        val * aux[wn0 + j * 16 + c] + xres[strideX * (size_t)b + o];
                }
            }
            __syncwarp();
        }
    }
}

static constexpr size_t pipe_smem(bool AROW, bool BROW) {
    int SA_R = AROW ? 128 : 64, SA_C = AROW ? 64 : 128;
    int SB_R = BROW ? 64 : 128, SB_C = BROW ? 128 : 64;
    return (size_t)2 * (SA_R * (SA_C + 8) + SB_R * (SB_C + 8)) * 2 +
           (size_t)4 * 256 * 4 + 512;
}

// ---------- register-prefetch GEMM (q/k projections) ----------
template<int BM, int BN, int BK, int WM, int WN, bool AROW, bool BROW>
__global__ void __launch_bounds__((BM / WM) * (BN / WN) * 32)
gemm_bf16(const __nv_bfloat16* __restrict__ A, size_t strideA, int lda,
          const __nv_bfloat16* __restrict__ Bm, size_t strideB, int ldb,
          void* __restrict__ Cm, size_t strideC, int ldc,
          const float* __restrict__ bias,
          int M, int N, int K)
{
    constexpr int WGM = BM / WM, WGN = BN / WN, NW = WGM * WGN;
    constexpr int MI = WM / 16, NI = WN / 16;
    constexpr int SA_R = AROW ? BM : BK, SA_C = AROW ? BK : BM;
    constexpr int SB_R = BROW ? BK : BN, SB_C = BROW ? BN : BK;
    constexpr int CVA = SA_C / 8, CVB = SB_C / 8;
    constexpr int ITA = (SA_R * CVA) / (NW * 32);
    constexpr int ITB = (SB_R * CVB) / (NW * 32);

    __shared__ __nv_bfloat16 smA[SA_R][SA_C + 8];
    __shared__ __nv_bfloat16 smB[SB_R][SB_C + 8];
    __shared__ float stage[NW][16 * 16];

    const int b = blockIdx.z;
    const __nv_bfloat16* Ab = A + strideA * (size_t)b;
    const __nv_bfloat16* Bb = Bm + strideB * (size_t)b;
    const size_t cb = strideC * (size_t)b;

    const int blockM = blockIdx.y * BM;
    const int blockN = blockIdx.x * BN;
    const int tid = threadIdx.x;
    const int wid = tid >> 5, lane = tid & 31;
    const int wm0 = (wid % WGM) * WM;
    const int wn0 = (wid / WGM) * WN;

    using ALayout = typename std::conditional<AROW, wmma::row_major, wmma::col_major>::type;
    using BLayout = typename std::conditional<BROW, wmma::row_major, wmma::col_major>::type;

    wmma::fragment<wmma::accumulator, 16, 16, 16, float> acc[MI][NI];
#pragma unroll
    for (int i = 0; i < MI; i++)
#pragma unroll
        for (int j = 0; j < NI; j++) wmma::fill_fragment(acc[i][j], 0.0f);

#pragma unroll
    for (int it = 0; it < ITA; ++it) {
        int idx = tid + it * NW * 32;
        int r = idx / CVA, cv = idx % CVA;
        const __nv_bfloat16* src = AROW
            ? Ab + (size_t)(blockM + r) * lda + cv * 8
            : Ab + (size_t)r * lda + blockM + cv * 8;
        *reinterpret_cast<uint4*>(&smA[r][cv * 8]) = *reinterpret_cast<const uint4*>(src);
    }
#pragma unroll
    for (int it = 0; it < ITB; ++it) {
        int idx = tid + it * NW * 32;
        int r = idx / CVB, cv = idx % CVB;
        const __nv_bfloat16* src = BROW
            ? Bb + (size_t)r * ldb + blockN + cv * 8
            : Bb + (size_t)(blockN + r) * ldb + cv * 8;
        *reinterpret_cast<uint4*>(&smB[r][cv * 8]) = *reinterpret_cast<const uint4*>(src);
    }
    __syncthreads();

    const int T = K / BK;
    for (int t = 0; t < T; ++t) {
        uint4 pra[ITA], prb[ITB];
        if (t + 1 < T) {
            const int k0 = (t + 1) * BK;
#pragma unroll
            for (int it = 0; it < ITA; ++it) {
                int idx = tid + it * NW * 32;
                int r = idx / CVA, cv = idx % CVA;
                const __nv_bfloat16* src = AROW
                    ? Ab + (size_t)(blockM + r) * lda + k0 + cv * 8
                    : Ab + (size_t)(k0 + r) * lda + blockM + cv * 8;
                pra[it] = *reinterpret_cast<const uint4*>(src);
            }
#pragma unroll
            for (int it = 0; it < ITB; ++it) {
                int idx = tid + it * NW * 32;
                int r = idx / CVB, cv = idx % CVB;
                const __nv_bfloat16* src = BROW
                    ? Bb + (size_t)(k0 + r) * ldb + blockN + cv * 8
                    : Bb + (size_t)(blockN + r) * ldb + k0 + cv * 8;
                prb[it] = *reinterpret_cast<const uint4*>(src);
            }
        }

#pragma unroll
        for (int kk = 0; kk < BK; kk += 16) {
            wmma::fragment<wmma::matrix_a, 16, 16, 16, __nv_bfloat16, ALayout> af[MI];
            wmma::fragment<wmma::matrix_b, 16, 16, 16, __nv_bfloat16, BLayout> bfr[NI];
#pragma unroll
            for (int i = 0; i < MI; i++) {
                const __nv_bfloat16* p = AROW ? &smA[wm0 + i * 16][kk]
                                              : &smA[kk][wm0 + i * 16];
                wmma::load_matrix_sync(af[i], p, SA_C + 8);
            }
#pragma unroll
            for (int j = 0; j < NI; j++) {
                const __nv_bfloat16* p = BROW ? &smB[kk][wn0 + j * 16]
                                              : &smB[wn0 + j * 16][kk];
                wmma::load_matrix_sync(bfr[j], p, SB_C + 8);
            }
#pragma unroll
            for (int i = 0; i < MI; i++)
#pragma unroll
                for (int j = 0; j < NI; j++)
                    wmma::mma_sync(acc[i][j], af[i], bfr[j], acc[i][j]);
        }
        __syncthreads();

        if (t + 1 < T) {
#pragma unroll
            for (int it = 0; it < ITA; ++it) {
                int idx = tid + it * NW * 32;
                int r = idx / CVA, cv = idx % CVA;
                *reinterpret_cast<uint4*>(&smA[r][cv * 8]) = pra[it];
            }
#pragma unroll
            for (int it = 0; it < ITB; ++it) {
                int idx = tid + it * NW * 32;
                int r = idx / CVB, cv = idx % CVB;
                *reinterpret_cast<uint4*>(&smB[r][cv * 8]) = prb[it];
            }
            __syncthreads();
        }
    }

#pragma unroll
    for (int i = 0; i < MI; i++) {
#pragma unroll
        for (int j = 0; j < NI; j++) {
            wmma::store_matrix_sync(&stage[wid][0], acc[i][j], 16, wmma::mem_row_major);
            __syncwarp();
            int rowBase = blockM + wm0 + i * 16;
            int colBase = blockN + wn0 + j * 16;
#pragma unroll
            for (int e = lane; e < 256; e += 32) {
                int r = e >> 4, c = e & 15;
                float val = stage[wid][e];
                size_t o = (size_t)(rowBase + r) * ldc + colBase + c;
                ((__nv_bfloat16*)Cm)[cb + o] = __float2bfloat16(val + bias[rowBase + r]);
            }
            __syncwarp();
        }
    }
}

// ---------------- launch ----------------
extern "C" void kernel_launch(void* const* d_in, const int* in_sizes, int n_in,
                              void* d_out, int out_size) {
    const float* x     = (const float*)d_in[0];
    const float* Wq    = (const float*)d_in[1];
    const float* bq    = (const float*)d_in[2];
    const float* Wk    = (const float*)d_in[3];
    const float* bk    = (const float*)d_in[4];
    const float* Wv    = (const float*)d_in[5];
    const float* bv    = (const float*)d_in[6];
    const float* gamma = (const float*)d_in[7];

    __nv_bfloat16 *xb, *wq, *wk, *wv, *q, *k, *v, *attn;
    float* rowsum;
    cudaGetSymbolAddress((void**)&xb, g_xb);
    cudaGetSymbolAddress((void**)&wq, g_Wq);
    cudaGetSymbolAddress((void**)&wk, g_Wk);
    cudaGetSymbolAddress((void**)&wv, g_Wv);
    cudaGetSymbolAddress((void**)&q, g_q);
    cudaGetSymbolAddress((void**)&k, g_k);
    cudaGetSymbolAddress((void**)&v, g_v);
    cudaGetSymbolAddress((void**)&attn, g_attn);
    cudaGetSymbolAddress((void**)&rowsum, g_rowsum);

    const size_t sX = (size_t)CCH * NPIX;
    const size_t sQ = (size_t)CQD * NPIX;
    const size_t sS = (size_t)NPIX * NPIX;

    // casts
    {
        size_t n4 = (size_t)BATCH * sX / 4;
        cast_kernel<<<(unsigned)((n4 + 255) / 256), 256>>>(x, xb, n4);
        size_t nq4 = (size_t)CQD * CCH / 4;
        cast_kernel<<<(unsigned)((nq4 + 255) / 256), 256>>>(Wq, wq, nq4);
        cast_kernel<<<(unsigned)((nq4 + 255) / 256), 256>>>(Wk, wk, nq4);
        size_t nv4 = (size_t)CCH * CCH / 4;
        cast_kernel<<<(unsigned)((nv4 + 255) / 256), 256>>>(Wv, wv, nv4);
    }

    // q = Wq @ xb + bq ; k = Wk @ xb + bk   [64 x 4096] per batch, bf16 out
    {
        dim3 g(NPIX / 128, CQD / 64, BATCH);
        gemm_bf16<64, 128, 64, 32, 32, true, true><<<g, 256>>>(
            wq, 0, CCH, xb, sX, NPIX, q, sQ, NPIX, bq, CQD, NPIX, CCH);
        gemm_bf16<64, 128, 64, 32, 32, true, true><<<g, 256>>>(
            wk, 0, CCH, xb, sX, NPIX, k, sQ, NPIX, bk, CQD, NPIX, CCH);
    }

    // v = Wv @ xb + bv   [512 x 4096] per batch, bf16 out
    {
        auto kfn = gemm_pipe<true, true, 1>;
        size_t sm = pipe_smem(true, true);
        cudaFuncSetAttribute(kfn, cudaFuncAttributeMaxDynamicSharedMemorySize, (int)sm);
        dim3 g(NPIX / 128, CCH / 128, BATCH);
        kfn<<<g, 128, sm>>>(wv, 0, CCH, xb, sX, NPIX, v, sX, NPIX, bv,
                            nullptr, nullptr, 0, nullptr, CCH, NPIX, CCH);
    }

    // attn = exp(q^T k)  (Q-resident pipelined kernel, plain epilogue)
    {
        cudaFuncSetAttribute(scores_pipe,
                             cudaFuncAttributeMaxDynamicSharedMemorySize, (int)SCORES_SMEM);
        dim3 g(8, NPIX / 128, BATCH);
        scores_pipe<<<g, 128, SCORES_SMEM>>>(q, k, attn);
    }

    // rowsum[b,i] = sum_j attn[b,i,j]
    rowsum_kernel<<<BATCH * NPIX, 128>>>(attn, rowsum);

    // out[c,i] = gamma/rowsum[i] * sum_j v[c,j]*attn[i,j] + x[c,i]  -> fp32
    {
        auto kfn = gemm_pipe<true, false, 2>;
        size_t sm = pipe_smem(true, false);
        cudaFuncSetAttribute(kfn, cudaFuncAttributeMaxDynamicSharedMemorySize, (int)sm);
        dim3 g(NPIX / 128, CCH / 128, BATCH);
        kfn<<<g, 128, sm>>>(v, sX, NPIX, attn, sS, NPIX, d_out, sX, NPIX, nullptr,
                            gamma, x, sX, rowsum, CCH, NPIX, NPIX);
    }
}

// round 14
// speedup vs baseline: 1.4798x; 1.0739x over previous

#include <cuda_runtime.h>
#include <cuda_bf16.h>
#include <mma.h>
#include <cstdint>
#include <cstddef>
#include <type_traits>

using namespace nvcuda;

#define BATCH 8
#define CCH   512
#define NPIX  4096
#define CQD   64

// ---------------- static scratch (no runtime allocation allowed) ----------------
__device__ __nv_bfloat16 g_xb[(size_t)BATCH * CCH * NPIX];       // x in bf16
__device__ __nv_bfloat16 g_Wqk[2 * CQD * CCH];                   // [Wq; Wk]
__device__ float         g_bqk[2 * CQD];                         // [bq; bk]
__device__ __nv_bfloat16 g_Wv[CCH * CCH];
__device__ __nv_bfloat16 g_qk[(size_t)BATCH * 2 * CQD * NPIX];   // [b, 128, NPIX]: q rows 0-63, k rows 64-127
__device__ __nv_bfloat16 g_v[(size_t)BATCH * CCH * NPIX];
__device__ __nv_bfloat16 g_attn[(size_t)BATCH * NPIX * NPIX];    // exp(scores), unnormalized
__device__ float         g_rspart[(size_t)BATCH * 8 * NPIX];     // per-jgroup rowsum partials
__device__ float         g_rowsum[(size_t)BATCH * NPIX];

// ---------------- helpers ----------------
__device__ __forceinline__ uint32_t smem_u32(const void* p) {
    uint32_t a;
    asm("{ .reg .u64 t; cvta.to.shared.u64 t, %1; cvt.u32.u64 %0, t; }" : "=r"(a) : "l"(p));
    return a;
}
__device__ __forceinline__ void cpa16(uint32_t dst, const void* src) {
    asm volatile("cp.async.cg.shared.global [%0], [%1], 16;" :: "r"(dst), "l"(src));
}
#define CP_COMMIT() asm volatile("cp.async.commit_group;" ::: "memory")
#define CP_WAIT(n)  asm volatile("cp.async.wait_group %0;" :: "n"(n) : "memory")

// ---------------- fp32 -> bf16 cast (vectorized) ----------------
__global__ void cast_kernel(const float* __restrict__ in,
                            __nv_bfloat16* __restrict__ out, size_t n4) {
    size_t i = (size_t)blockIdx.x * blockDim.x + threadIdx.x;
    if (i < n4) {
        float4 f = reinterpret_cast<const float4*>(in)[i];
        __nv_bfloat162 a = __floats2bfloat162_rn(f.x, f.y);
        __nv_bfloat162 b = __floats2bfloat162_rn(f.z, f.w);
        uint2 u;
        u.x = *reinterpret_cast<unsigned*>(&a);
        u.y = *reinterpret_cast<unsigned*>(&b);
        reinterpret_cast<uint2*>(out)[i] = u;
    }
}

// ---------------- bias concat ----------------
__global__ void concat_bias(const float* __restrict__ bq, const float* __restrict__ bk,
                            float* __restrict__ bqk) {
    int t = threadIdx.x;
    bqk[t] = (t < CQD) ? bq[t] : bk[t - CQD];
}

// ---------------- rowsum partial reduce: 8 jgroups -> 1 ----------------
__global__ void rs_reduce(const float* __restrict__ rspart,
                          float* __restrict__ rowsum) {
    int idx = blockIdx.x * blockDim.x + threadIdx.x;
    if (idx < BATCH * NPIX) {
        int b = idx / NPIX, i = idx - b * NPIX;
        float s = 0.0f;
#pragma unroll
        for (int jg = 0; jg < 8; ++jg)
            s += rspart[((size_t)b * 8 + jg) * NPIX + i];
        rowsum[idx] = s;
    }
}

// ============ scores kernel: Q-resident, pipelined, register-fused rowsum ============
// attn[i,j] = exp(sum_d q[d,i]*k[d,j]).  128 threads, 4 warps of 64x64.
__global__ void __launch_bounds__(128, 2)
scores_pipe(const __nv_bfloat16* __restrict__ qk,
            __nv_bfloat16* __restrict__ attn, float* __restrict__ rspart)
{
    constexpr int LDS = 136;                 // 128 + 8 pad (halves)
    constexpr int TILE = 64 * LDS;
    extern __shared__ char dsm[];
    __nv_bfloat16* smA = reinterpret_cast<__nv_bfloat16*>(dsm);     // [64][136]
    __nv_bfloat16* smB = smA + TILE;                                // 2 x [64][136]
    float* stage = reinterpret_cast<float*>(smB + 2 * TILE);        // [4][256]
    float* auxRS = stage + 4 * 256;                                 // [2][128]
    const uint32_t smA_u = smem_u32(smA);
    const uint32_t smB_u = smem_u32(smB);

    const int b = blockIdx.z;
    const int jg = blockIdx.x;               // 0..7, j in [jg*512, jg*512+512)
    const int i0 = blockIdx.y * 128;
    const int tid = threadIdx.x;
    const int wid = tid >> 5, lane = tid & 31;
    const int wm0 = (wid & 1) * 64;
    const int wn0 = (wid >> 1) * 64;

    const __nv_bfloat16* qb = qk + (size_t)b * (2 * CQD) * NPIX;          // q rows
    const __nv_bfloat16* kb = qb + (size_t)CQD * NPIX;                    // k rows
    __nv_bfloat16* attnb = attn + (size_t)b * NPIX * NPIX;

    float part[4][4];
#pragma unroll
    for (int i = 0; i < 4; i++)
#pragma unroll
        for (int p = 0; p < 4; p++) part[i][p] = 0.0f;

    // prologue: A (q block, resident) + B(j-tile 0)
#pragma unroll
    for (int it = 0; it < 8; ++it) {
        int idx = tid + it * 128;
        int r = idx >> 4, cv = idx & 15;
        cpa16(smA_u + (uint32_t)(r * LDS + cv * 8) * 2,
              qb + (size_t)r * NPIX + i0 + cv * 8);
    }
    {
        const int j0 = jg * 512;
#pragma unroll
        for (int it = 0; it < 8; ++it) {
            int idx = tid + it * 128;
            int r = idx >> 4, cv = idx & 15;
            cpa16(smB_u + (uint32_t)(r * LDS + cv * 8) * 2,
                  kb + (size_t)r * NPIX + j0 + cv * 8);
        }
    }
    CP_COMMIT();

    for (int jt = 0; jt < 4; ++jt) {
        const int cur = jt & 1;
        if (jt + 1 < 4) {
            const int j0 = jg * 512 + (jt + 1) * 128;
            const uint32_t bbuf = smB_u + (uint32_t)((cur ^ 1) * TILE) * 2;
#pragma unroll
            for (int it = 0; it < 8; ++it) {
                int idx = tid + it * 128;
                int r = idx >> 4, cv = idx & 15;
                cpa16(bbuf + (uint32_t)(r * LDS + cv * 8) * 2,
                      kb + (size_t)r * NPIX + j0 + cv * 8);
            }
            CP_COMMIT();
            CP_WAIT(1);
        } else {
            CP_WAIT(0);
        }
        __syncthreads();

        // MMA: S(128x128) = A^T * B over K=64
        wmma::fragment<wmma::accumulator, 16, 16, 16, float> acc[4][4];
#pragma unroll
        for (int i = 0; i < 4; i++)
#pragma unroll
            for (int j = 0; j < 4; j++) wmma::fill_fragment(acc[i][j], 0.0f);

        const __nv_bfloat16* b0 = smB + cur * TILE;
#pragma unroll
        for (int kk = 0; kk < 64; kk += 16) {
            wmma::fragment<wmma::matrix_a, 16, 16, 16, __nv_bfloat16, wmma::col_major> af[4];
            wmma::fragment<wmma::matrix_b, 16, 16, 16, __nv_bfloat16, wmma::row_major> bfr[4];
#pragma unroll
            for (int i = 0; i < 4; i++)
                wmma::load_matrix_sync(af[i], smA + kk * LDS + wm0 + i * 16, LDS);
#pragma unroll
            for (int j = 0; j < 4; j++)
                wmma::load_matrix_sync(bfr[j], b0 + kk * LDS + wn0 + j * 16, LDS);
#pragma unroll
            for (int i = 0; i < 4; i++)
#pragma unroll
                for (int j = 0; j < 4; j++)
                    wmma::mma_sync(acc[i][j], af[i], bfr[j], acc[i][j]);
        }
        __syncthreads();

        // epilogue: exp -> attn (bf16x2 stores), register rowsum partials
        const int jbase = jg * 512 + jt * 128;
#pragma unroll
        for (int i = 0; i < 4; i++) {
#pragma unroll
            for (int j = 0; j < 4; j++) {
                wmma::store_matrix_sync(&stage[wid * 256], acc[i][j], 16, wmma::mem_row_major);
                __syncwarp();
                int rowBase = i0 + wm0 + i * 16;
                int colBase = jbase + wn0 + j * 16;
#pragma unroll
                for (int p = 0; p < 4; ++p) {
                    int pi = lane + 32 * p;          // pair index 0..127
                    int r = pi >> 3, c = (pi & 7) * 2;
                    float e0 = __expf(stage[wid * 256 + r * 16 + c]);
                    float e1 = __expf(stage[wid * 256 + r * 16 + c + 1]);
                    part[i][p] += e0 + e1;
                    __nv_bfloat162 h = __floats2bfloat162_rn(e0, e1);
                    *reinterpret_cast<uint32_t*>(
                        &attnb[(size_t)(rowBase + r) * NPIX + colBase + c]) =
                        *reinterpret_cast<uint32_t*>(&h);
                }
                __syncwarp();
            }
        }
        __syncthreads();
    }

    // end-of-kernel rowsum reduction: 8-lane groups share a row
#pragma unroll
    for (int i = 0; i < 4; i++) {
#pragma unroll
        for (int p = 0; p < 4; p++) {
            float s = part[i][p];
            s += __shfl_xor_sync(0xffffffffu, s, 1);
            s += __shfl_xor_sync(0xffffffffu, s, 2);
            s += __shfl_xor_sync(0xffffffffu, s, 4);
            if ((lane & 7) == 0)
                auxRS[(wid >> 1) * 128 + wm0 + i * 16 + (lane >> 3) + 4 * p] = s;
        }
    }
    __syncthreads();
    rspart[((size_t)b * 8 + jg) * NPIX + i0 + tid] = auxRS[tid] + auxRS[128 + tid];
}
static constexpr size_t SCORES_SMEM =
    (size_t)3 * 64 * 136 * 2 + 4 * 256 * 4 + 2 * 128 * 4 + 128;

// ============ pipelined 128x128 GEMM: cp.async 2-stage, 4 warps of 64x64 ============
// EPI 1: bf16 (acc + bias[row]); EPI 2: fp32 (gamma/rowsum[col]*acc + xres)
template<bool AROW, bool BROW, int EPI>
__global__ void __launch_bounds__(128, 2)
gemm_pipe(const __nv_bfloat16* __restrict__ A, size_t strideA, int lda,
          const __nv_bfloat16* __restrict__ Bm, size_t strideB, int ldb,
          void* __restrict__ Cm, size_t strideC, int ldc,
          const float* __restrict__ bias,
          const float* __restrict__ gamma,
          const float* __restrict__ xres, size_t strideX,
          const float* __restrict__ rowsum,
          int M, int N, int K)
{
    constexpr int BM = 128, BN = 128, BK = 64, WM = 64, WN = 64;
    constexpr int WGM = BM / WM;
    constexpr int MI = WM / 16, NI = WN / 16;
    constexpr int SA_R = AROW ? BM : BK, SA_C = AROW ? BK : BM;
    constexpr int SB_R = BROW ? BK : BN, SB_C = BROW ? BN : BK;
    constexpr int LDA_S = SA_C + 8, LDB_S = SB_C + 8;
    constexpr int AELEM = SA_R * LDA_S;
    constexpr int BELEM = SB_R * LDB_S;
    constexpr int CVA = SA_C / 8, CVB = SB_C / 8;
    constexpr int ITA = (SA_R * CVA) / 128;
    constexpr int ITB = (SB_R * CVB) / 128;

    extern __shared__ char dsm[];
    __nv_bfloat16* smA = reinterpret_cast<__nv_bfloat16*>(dsm);
    __nv_bfloat16* smB = smA + 2 * AELEM;
    float* stage = reinterpret_cast<float*>(smB + 2 * BELEM);
    float* aux = stage + 4 * 256;
    const uint32_t smA_u = smem_u32(smA);
    const uint32_t smB_u = smem_u32(smB);

    const int b = blockIdx.z;
    const __nv_bfloat16* Ab = A + strideA * (size_t)b;
    const __nv_bfloat16* Bb = Bm + strideB * (size_t)b;
    const size_t cb = strideC * (size_t)b;

    const int blockM = blockIdx.y * BM;
    const int blockN = blockIdx.x * BN;
    const int tid = threadIdx.x;
    const int wid = tid >> 5, lane = tid & 31;
    const int wm0 = (wid % WGM) * WM;
    const int wn0 = (wid / WGM) * WN;

    using ALayout = typename std::conditional<AROW, wmma::row_major, wmma::col_major>::type;
    using BLayout = typename std::conditional<BROW, wmma::row_major, wmma::col_major>::type;

    wmma::fragment<wmma::accumulator, 16, 16, 16, float> acc[MI][NI];
#pragma unroll
    for (int i = 0; i < MI; i++)
#pragma unroll
        for (int j = 0; j < NI; j++) wmma::fill_fragment(acc[i][j], 0.0f);

#pragma unroll
    for (int it = 0; it < ITA; ++it) {
        int idx = tid + it * 128;
        int r = idx / CVA, cv = idx % CVA;
        const __nv_bfloat16* src = AROW
            ? Ab + (size_t)(blockM + r) * lda + cv * 8
            : Ab + (size_t)r * lda + blockM + cv * 8;
        cpa16(smA_u + (uint32_t)(r * LDA_S + cv * 8) * 2, src);
    }
#pragma unroll
    for (int it = 0; it < ITB; ++it) {
        int idx = tid + it * 128;
        int r = idx / CVB, cv = idx % CVB;
        const __nv_bfloat16* src = BROW
            ? Bb + (size_t)r * ldb + blockN + cv * 8
            : Bb + (size_t)(blockN + r) * ldb + cv * 8;
        cpa16(smB_u + (uint32_t)(r * LDB_S + cv * 8) * 2, src);
    }
    CP_COMMIT();

    const int T = K / BK;
    for (int t = 0; t < T; ++t) {
        const int cur = t & 1;
        if (t + 1 < T) {
            const int k0 = (t + 1) * BK;
            const uint32_t abuf = smA_u + (uint32_t)((cur ^ 1) * AELEM) * 2;
            const uint32_t bbuf = smB_u + (uint32_t)((cur ^ 1) * BELEM) * 2;
#pragma unroll
            for (int it = 0; it < ITA; ++it) {
                int idx = tid + it * 128;
                int r = idx / CVA, cv = idx % CVA;
                const __nv_bfloat16* src = AROW
                    ? Ab + (size_t)(blockM + r) * lda + k0 + cv * 8
                    : Ab + (size_t)(k0 + r) * lda + blockM + cv * 8;
                cpa16(abuf + (uint32_t)(r * LDA_S + cv * 8) * 2, src);
            }
#pragma unroll
            for (int it = 0; it < ITB; ++it) {
                int idx = tid + it * 128;
                int r = idx / CVB, cv = idx % CVB;
                const __nv_bfloat16* src = BROW
                    ? Bb + (size_t)(k0 + r) * ldb + blockN + cv * 8
                    : Bb + (size_t)(blockN + r) * ldb + k0 + cv * 8;
                cpa16(bbuf + (uint32_t)(r * LDB_S + cv * 8) * 2, src);
            }
            CP_COMMIT();
            CP_WAIT(1);
        } else {
            CP_WAIT(0);
        }
        __syncthreads();

        const __nv_bfloat16* a0 = smA + cur * AELEM;
        const __nv_bfloat16* b0 = smB + cur * BELEM;
#pragma unroll
        for (int kk = 0; kk < BK; kk += 16) {
            wmma::fragment<wmma::matrix_a, 16, 16, 16, __nv_bfloat16, ALayout> af[MI];
            wmma::fragment<wmma::matrix_b, 16, 16, 16, __nv_bfloat16, BLayout> bfr[NI];
#pragma unroll
            for (int i = 0; i < MI; i++) {
                const __nv_bfloat16* p = AROW ? a0 + (wm0 + i * 16) * LDA_S + kk
                                              : a0 + kk * LDA_S + wm0 + i * 16;
                wmma::load_matrix_sync(af[i], p, LDA_S);
            }
#pragma unroll
            for (int j = 0; j < NI; j++) {
                const __nv_bfloat16* p = BROW ? b0 + kk * LDB_S + wn0 + j * 16
                                              : b0 + (wn0 + j * 16) * LDB_S + kk;
                wmma::load_matrix_sync(bfr[j], p, LDB_S);
            }
#pragma unroll
            for (int i = 0; i < MI; i++)
#pragma unroll
                for (int j = 0; j < NI; j++)
                    wmma::mma_sync(acc[i][j], af[i], bfr[j], acc[i][j]);
        }
        __syncthreads();
    }

    if (EPI == 2) {
        aux[tid] = gamma[0] / rowsum[(size_t)b * N + blockN + tid];
        __syncthreads();
    }

#pragma unroll
    for (int i = 0; i < MI; i++) {
#pragma unroll
        for (int j = 0; j < NI; j++) {
            wmma::store_matrix_sync(&stage[wid * 256], acc[i][j], 16, wmma::mem_row_major);
            __syncwarp();
            int rowBase = blockM + wm0 + i * 16;
            int colBase = blockN + wn0 + j * 16;
#pragma unroll
            for (int e = lane; e < 256; e += 32) {
                int r = e >> 4, c = e & 15;
                float val = stage[wid * 256 + e];
                size_t o = (size_t)(rowBase + r) * ldc + colBase + c;
                if (EPI == 1) {
                    ((__nv_bfloat16*)Cm)[cb + o] = __float2bfloat16(val + bias[rowBase + r]);
                } else {  // EPI 2
                    ((float*)Cm)[cb + o] =
                        val * aux[wn0 + j * 16 + c] + xres[strideX * (size_t)b + o];
                }
            }
            __syncwarp();
        }
    }
}

static constexpr size_t pipe_smem(bool AROW, bool BROW) {
    int SA_R = AROW ? 128 : 64, SA_C = AROW ? 64 : 128;
    int SB_R = BROW ? 64 : 128, SB_C = BROW ? 128 : 64;
    return (size_t)2 * (SA_R * (SA_C + 8) + SB_R * (SB_C + 8)) * 2 +
           (size_t)4 * 256 * 4 + 512;
}

// ---------------- launch ----------------
extern "C" void kernel_launch(void* const* d_in, const int* in_sizes, int n_in,
                              void* d_out, int out_size) {
    const float* x     = (const float*)d_in[0];
    const float* Wq    = (const float*)d_in[1];
    const float* bq    = (const float*)d_in[2];
    const float* Wk    = (const float*)d_in[3];
    const float* bk    = (const float*)d_in[4];
    const float* Wv    = (const float*)d_in[5];
    const float* bv    = (const float*)d_in[6];
    const float* gamma = (const float*)d_in[7];

    __nv_bfloat16 *xb, *wqk, *wv, *qk, *v, *attn;
    float *bqk, *rspart, *rowsum;
    cudaGetSymbolAddress((void**)&xb, g_xb);
    cudaGetSymbolAddress((void**)&wqk, g_Wqk);
    cudaGetSymbolAddress((void**)&bqk, g_bqk);
    cudaGetSymbolAddress((void**)&wv, g_Wv);
    cudaGetSymbolAddress((void**)&qk, g_qk);
    cudaGetSymbolAddress((void**)&v, g_v);
    cudaGetSymbolAddress((void**)&attn, g_attn);
    cudaGetSymbolAddress((void**)&rspart, g_rspart);
    cudaGetSymbolAddress((void**)&rowsum, g_rowsum);

    const size_t sX = (size_t)CCH * NPIX;
    const size_t sQK = (size_t)2 * CQD * NPIX;
    const size_t sS = (size_t)NPIX * NPIX;

    // casts + bias concat
    {
        size_t n4 = (size_t)BATCH * sX / 4;
        cast_kernel<<<(unsigned)((n4 + 255) / 256), 256>>>(x, xb, n4);
        size_t nq4 = (size_t)CQD * CCH / 4;
        cast_kernel<<<(unsigned)((nq4 + 255) / 256), 256>>>(Wq, wqk, nq4);
        cast_kernel<<<(unsigned)((nq4 + 255) / 256), 256>>>(Wk, wqk + CQD * CCH, nq4);
        size_t nv4 = (size_t)CCH * CCH / 4;
        cast_kernel<<<(unsigned)((nv4 + 255) / 256), 256>>>(Wv, wv, nv4);
        concat_bias<<<1, 128>>>(bq, bk, bqk);
    }

    // [q;k] = [Wq;Wk] @ xb + [bq;bk]   one M=128 GEMM per batch, bf16 out
    {
        auto kfn = gemm_pipe<true, true, 1>;
        size_t sm = pipe_smem(true, true);
        cudaFuncSetAttribute(kfn, cudaFuncAttributeMaxDynamicSharedMemorySize, (int)sm);
        dim3 g(NPIX / 128, 1, BATCH);
        kfn<<<g, 128, sm>>>(wqk, 0, CCH, xb, sX, NPIX, qk, sQK, NPIX, bqk,
                            nullptr, nullptr, 0, nullptr, 2 * CQD, NPIX, CCH);
    }

    // v = Wv @ xb + bv   [512 x 4096] per batch, bf16 out
    {
        auto kfn = gemm_pipe<true, true, 1>;
        size_t sm = pipe_smem(true, true);
        cudaFuncSetAttribute(kfn, cudaFuncAttributeMaxDynamicSharedMemorySize, (int)sm);
        dim3 g(NPIX / 128, CCH / 128, BATCH);
        kfn<<<g, 128, sm>>>(wv, 0, CCH, xb, sX, NPIX, v, sX, NPIX, bv,
                            nullptr, nullptr, 0, nullptr, CCH, NPIX, CCH);
    }

    // attn = exp(q^T k) with register-fused partial rowsums
    {
        cudaFuncSetAttribute(scores_pipe,
                             cudaFuncAttributeMaxDynamicSharedMemorySize, (int)SCORES_SMEM);
        dim3 g(8, NPIX / 128, BATCH);
        scores_pipe<<<g, 128, SCORES_SMEM>>>(qk, attn, rspart);
    }

    // rowsum = sum of 8 partials
    rs_reduce<<<(BATCH * NPIX + 255) / 256, 256>>>(rspart, rowsum);

    // out[c,i] = gamma/rowsum[i] * sum_j v[c,j]*attn[i,j] + x[c,i]  -> fp32
    {
        auto kfn = gemm_pipe<true, false, 2>;
        size_t sm = pipe_smem(true, false);
        cudaFuncSetAttribute(kfn, cudaFuncAttributeMaxDynamicSharedMemorySize, (int)sm);
        dim3 g(NPIX / 128, CCH / 128, BATCH);
        kfn<<<g, 128, sm>>>(v, sX, NPIX, attn, sS, NPIX, d_out, sX, NPIX, nullptr,
                            gamma, x, sX, rowsum, CCH, NPIX, NPIX);
    }
}